// round 3
// baseline (speedup 1.0000x reference)
#include <cuda_runtime.h>

#define Nn 50000
#define Ee 800000

typedef unsigned long long u64;

// ---------------- scratch (device globals; no runtime allocation) ----------
__device__ float g_feat[(size_t)Nn * 256];  // [N,256]
__device__ float g_el[Nn * 8];
__device__ float g_er[Nn * 8];
__device__ float g_ef1[(size_t)Ee * 32];    // [E,32]
__device__ float g_q[(size_t)Ee * 8];       // p * ee
__device__ float g_esum[Nn * 8];

// ---------------- packed f32x2 helpers --------------------------------------
__device__ __forceinline__ u64 pk(float x, float y) {
    u64 r; asm("mov.b64 %0, {%1, %2};" : "=l"(r) : "f"(x), "f"(y)); return r;
}
__device__ __forceinline__ float2 upk(u64 v) {
    float2 f; asm("mov.b64 {%0, %1}, %2;" : "=f"(f.x), "=f"(f.y) : "l"(v)); return f;
}
__device__ __forceinline__ void fma2(u64& d, u64 a, u64 b) {
    asm("fma.rn.f32x2 %0, %1, %2, %0;" : "+l"(d) : "l"(a), "l"(b));
}

__device__ __forceinline__ float ssp(float x) {
    // softplus(x) - ln2, numerically stable
    float e = __expf(-fabsf(x));
    return fmaxf(x, 0.f) + __logf(1.f + e) - 0.69314718056f;
}

// ---------------- K0: init output with bias, zero esum ---------------------
__global__ void k_init(float* __restrict__ out, const float* __restrict__ bias) {
    int stride = gridDim.x * blockDim.x;
    for (int i = blockIdx.x * blockDim.x + threadIdx.x; i < Nn * 256; i += stride)
        out[i] = bias[i & 255];
    for (int j = blockIdx.x * blockDim.x + threadIdx.x; j < Nn * 8; j += stride)
        g_esum[j] = 0.f;
}

// ---------------- K1: feat = nfeat @ W_fc^T  (50000x256x128) ---------------
// Tile: 128 rows x 64 cols per block, 256 threads, 8r x 4c per thread.
__global__ void __launch_bounds__(256) k_feat(const float* __restrict__ A,
                                              const float* __restrict__ B) {
    __shared__ float As[128 * 20];   // 128 rows x 16k (pad 20)     10.2 KB
    __shared__ float Bs[128 * 68];   // [k][64 cols pad 68]         34.8 KB
    int m0 = blockIdx.x * 128, n0 = blockIdx.y * 64;
    int t = threadIdx.x;
    // stage B block (64 rows of W, full K=128), transposed
    for (int i = t; i < 2048; i += 256) {
        int n = i >> 5, k4 = (i & 31) * 4;
        float4 v = *(const float4*)&B[(size_t)(n0 + n) * 128 + k4];
        Bs[(k4 + 0) * 68 + n] = v.x; Bs[(k4 + 1) * 68 + n] = v.y;
        Bs[(k4 + 2) * 68 + n] = v.z; Bs[(k4 + 3) * 68 + n] = v.w;
    }
    int tx = t & 15, ty = t >> 4;    // tx: cols (4), ty: rows (8)
    u64 acc[4][4];
#pragma unroll
    for (int p = 0; p < 4; p++)
#pragma unroll
        for (int c = 0; c < 4; c++) acc[p][c] = 0ull;

    for (int k0 = 0; k0 < 128; k0 += 16) {
        __syncthreads();
        for (int i = t; i < 512; i += 256) {   // 128 rows x 16k = 512 float4
            int r = i >> 2, kq = (i & 3) * 4;
            int gm = m0 + r;
            float4 v = make_float4(0.f, 0.f, 0.f, 0.f);
            if (gm < Nn) v = *(const float4*)&A[(size_t)gm * 128 + k0 + kq];
            *(float4*)&As[r * 20 + kq] = v;
        }
        __syncthreads();
#pragma unroll
        for (int kk = 0; kk < 16; kk += 4) {
            float4 a4[8];
#pragma unroll
            for (int i = 0; i < 8; i++) a4[i] = *(float4*)&As[(ty * 8 + i) * 20 + kk];
#pragma unroll
            for (int k2 = 0; k2 < 4; k2++) {
                float4 b4 = *(float4*)&Bs[(k0 + kk + k2) * 68 + tx * 4];
                u64 bb0 = pk(b4.x, b4.x), bb1 = pk(b4.y, b4.y);
                u64 bb2 = pk(b4.z, b4.z), bb3 = pk(b4.w, b4.w);
#pragma unroll
                for (int p = 0; p < 4; p++) {
                    u64 ap = pk((&a4[2 * p].x)[k2], (&a4[2 * p + 1].x)[k2]);
                    fma2(acc[p][0], ap, bb0); fma2(acc[p][1], ap, bb1);
                    fma2(acc[p][2], ap, bb2); fma2(acc[p][3], ap, bb3);
                }
            }
        }
    }
#pragma unroll
    for (int p = 0; p < 4; p++) {
        float2 c0 = upk(acc[p][0]), c1 = upk(acc[p][1]);
        float2 c2 = upk(acc[p][2]), c3 = upk(acc[p][3]);
        int r0 = m0 + ty * 8 + 2 * p;
        if (r0 < Nn)
            *(float4*)&g_feat[(size_t)r0 * 256 + n0 + tx * 4] = make_float4(c0.x, c1.x, c2.x, c3.x);
        if (r0 + 1 < Nn)
            *(float4*)&g_feat[(size_t)(r0 + 1) * 256 + n0 + tx * 4] = make_float4(c0.y, c1.y, c2.y, c3.y);
    }
}

// ---------------- K1b: el/er per (node,head) --------------------------------
__global__ void k_elr(const float* __restrict__ al, const float* __restrict__ ar) {
    int idx = blockIdx.x * blockDim.x + threadIdx.x;
    if (idx >= Nn * 8) return;
    int node = idx >> 3, h = idx & 7;
    const float* f = &g_feat[(size_t)node * 256 + h * 32];
    float pl = 0.f, pr = 0.f;
#pragma unroll
    for (int j = 0; j < 8; j++) {
        float4 v  = *(const float4*)&f[j * 4];
        float4 l  = *(const float4*)&al[h * 32 + j * 4];
        float4 rr = *(const float4*)&ar[h * 32 + j * 4];
        pl += v.x * l.x + v.y * l.y + v.z * l.z + v.w * l.w;
        pr += v.x * rr.x + v.y * rr.y + v.z * rr.z + v.w * rr.w;
    }
    g_el[idx] = pl;
    g_er[idx] = pr;
}

// ---------------- K2: ef1 = ssp(efeat @ W_e1^T + b)  (800000x32x128) -------
// Tile: 256 rows x 32 cols per block, 256 threads, 8r x 4c per thread.
__global__ void __launch_bounds__(256) k_ef1(const float* __restrict__ Eg,
                                             const float* __restrict__ W,
                                             const float* __restrict__ bia) {
    __shared__ float As[256 * 20];   // 256 rows x 16k (pad 20)  20.5 KB
    __shared__ float Bs[128 * 36];   // [k][32 cols pad 36]      18.4 KB
    __shared__ float sb1[32];
    int m0 = blockIdx.x * 256;
    int t = threadIdx.x;
    if (t < 32) sb1[t] = bia[t];
    for (int i = t; i < 1024; i += 256) {     // W [32,128] transposed
        int n = i >> 5, k4 = (i & 31) * 4;
        float4 v = *(const float4*)&W[n * 128 + k4];
        Bs[(k4 + 0) * 36 + n] = v.x; Bs[(k4 + 1) * 36 + n] = v.y;
        Bs[(k4 + 2) * 36 + n] = v.z; Bs[(k4 + 3) * 36 + n] = v.w;
    }
    int tx = t & 7, ty = t >> 3;     // tx: cols (4 of 32), ty: rows (8 of 256)
    u64 acc[4][4];
#pragma unroll
    for (int p = 0; p < 4; p++)
#pragma unroll
        for (int c = 0; c < 4; c++) acc[p][c] = 0ull;

    for (int k0 = 0; k0 < 128; k0 += 16) {
        __syncthreads();
        for (int i = t; i < 1024; i += 256) {  // 256 rows x 16k = 1024 float4
            int r = i >> 2, kq = (i & 3) * 4;
            *(float4*)&As[r * 20 + kq] =
                *(const float4*)&Eg[(size_t)(m0 + r) * 128 + k0 + kq];
        }
        __syncthreads();
#pragma unroll
        for (int kk = 0; kk < 16; kk += 4) {
            float4 a4[8];
#pragma unroll
            for (int i = 0; i < 8; i++) a4[i] = *(float4*)&As[(ty * 8 + i) * 20 + kk];
#pragma unroll
            for (int k2 = 0; k2 < 4; k2++) {
                float4 b4 = *(float4*)&Bs[(k0 + kk + k2) * 36 + tx * 4];
                u64 bb0 = pk(b4.x, b4.x), bb1 = pk(b4.y, b4.y);
                u64 bb2 = pk(b4.z, b4.z), bb3 = pk(b4.w, b4.w);
#pragma unroll
                for (int p = 0; p < 4; p++) {
                    u64 ap = pk((&a4[2 * p].x)[k2], (&a4[2 * p + 1].x)[k2]);
                    fma2(acc[p][0], ap, bb0); fma2(acc[p][1], ap, bb1);
                    fma2(acc[p][2], ap, bb2); fma2(acc[p][3], ap, bb3);
                }
            }
        }
    }
#pragma unroll
    for (int p = 0; p < 4; p++) {
        float2 c0 = upk(acc[p][0]), c1 = upk(acc[p][1]);
        float2 c2 = upk(acc[p][2]), c3 = upk(acc[p][3]);
        float b0 = sb1[tx * 4 + 0], b1 = sb1[tx * 4 + 1];
        float b2 = sb1[tx * 4 + 2], b3 = sb1[tx * 4 + 3];
        int r0 = m0 + ty * 8 + 2 * p;
        *(float4*)&g_ef1[(size_t)r0 * 32 + tx * 4] =
            make_float4(ssp(c0.x + b0), ssp(c1.x + b1), ssp(c2.x + b2), ssp(c3.x + b3));
        *(float4*)&g_ef1[(size_t)(r0 + 1) * 32 + tx * 4] =
            make_float4(ssp(c0.y + b0), ssp(c1.y + b1), ssp(c2.y + b2), ssp(c3.y + b3));
    }
}

// ---------------- K3: per-edge fused MLP2 + ee + exp-logit -----------------
// warp handles 8 edges; lane owns outputs {lane*4+u} and {128+lane*4+u}
__global__ void __launch_bounds__(256) k_edge(const float* __restrict__ rij,
                                              const int* __restrict__ src,
                                              const int* __restrict__ dst,
                                              const float* __restrict__ W2,
                                              const float* __restrict__ b2,
                                              const float* __restrict__ attn_e) {
    __shared__ float WT[32 * 260];   // [k][o], padded row stride 260
    __shared__ float sb2[256], sae[256];
    __shared__ float sef[8][256];    // [warp][8 edges * 32]
    int t = threadIdx.x;
    for (int i = t; i < 8192; i += 256) {
        int o = i >> 5, k = i & 31;
        WT[k * 260 + o] = W2[i];
    }
    sb2[t] = b2[t];
    sae[t] = attn_e[t];
    __syncthreads();

    int wid = t >> 5, lane = t & 31;
    int warp_g = blockIdx.x * 8 + wid;
    int nwarps = gridDim.x * 8;

    for (int e0 = warp_g * 8; e0 < Ee; e0 += nwarps * 8) {
        __syncwarp();
#pragma unroll
        for (int le = 0; le < 8; le++)
            sef[wid][le * 32 + lane] = g_ef1[(size_t)(e0 + le) * 32 + lane];
        __syncwarp();

        // acc2[le][p]: packed pairs (w0.xy),(w0.zw),(w1.xy),(w1.zw)
        u64 acc2[8][4];
#pragma unroll
        for (int le = 0; le < 8; le++)
#pragma unroll
            for (int p = 0; p < 4; p++) acc2[le][p] = 0ull;

#pragma unroll
        for (int k = 0; k < 32; k++) {
            float4 w0 = *(float4*)&WT[k * 260 + lane * 4];
            float4 w1 = *(float4*)&WT[k * 260 + 128 + lane * 4];
            u64 wp0 = pk(w0.x, w0.y), wp1 = pk(w0.z, w0.w);
            u64 wp2 = pk(w1.x, w1.y), wp3 = pk(w1.z, w1.w);
#pragma unroll
            for (int le = 0; le < 8; le++) {
                float a = sef[wid][le * 32 + k];
                u64 aa = pk(a, a);
                fma2(acc2[le][0], aa, wp0); fma2(acc2[le][1], aa, wp1);
                fma2(acc2[le][2], aa, wp2); fma2(acc2[le][3], aa, wp3);
            }
        }

#pragma unroll
        for (int le = 0; le < 8; le++) {
            int e = e0 + le;
            float r = rij[e];
            float cw = (r < 5.f) ? 0.5f * (__cosf(0.62831853072f * r) + 1.f) : 0.f;
            float2 a0 = upk(acc2[le][0]), a1 = upk(acc2[le][1]);
            float2 a2 = upk(acc2[le][2]), a3 = upk(acc2[le][3]);
            int o1 = lane * 4, o2 = o1 + 128;
            float p1 = ssp(a0.x + sb2[o1 + 0]) * sae[o1 + 0]
                     + ssp(a0.y + sb2[o1 + 1]) * sae[o1 + 1]
                     + ssp(a1.x + sb2[o1 + 2]) * sae[o1 + 2]
                     + ssp(a1.y + sb2[o1 + 3]) * sae[o1 + 3];
            float p2 = ssp(a2.x + sb2[o2 + 0]) * sae[o2 + 0]
                     + ssp(a2.y + sb2[o2 + 1]) * sae[o2 + 1]
                     + ssp(a3.x + sb2[o2 + 2]) * sae[o2 + 2]
                     + ssp(a3.y + sb2[o2 + 3]) * sae[o2 + 3];
            p1 *= cw; p2 *= cw;
#pragma unroll
            for (int s = 1; s < 8; s <<= 1) {
                p1 += __shfl_xor_sync(0xffffffffu, p1, s);
                p2 += __shfl_xor_sync(0xffffffffu, p2, s);
            }
            if ((lane & 7) == 0) {
                int sN = src[e], dN = dst[e];
                int h1 = lane >> 3;
                int h2 = h1 + 4;
                float l1 = g_el[sN * 8 + h1] + g_er[dN * 8 + h1] + p1;
                float l2 = g_el[sN * 8 + h2] + g_er[dN * 8 + h2] + p2;
                l1 = (l1 > 0.f) ? l1 : 0.2f * l1;
                l2 = (l2 > 0.f) ? l2 : 0.2f * l2;
                float pp1 = __expf(l1);
                float pp2 = __expf(l2);
                g_q[(size_t)e * 8 + h1] = pp1 * p1;
                g_q[(size_t)e * 8 + h2] = pp2 * p2;
                atomicAdd(&g_esum[dN * 8 + h1], pp1);
                atomicAdd(&g_esum[dN * 8 + h2], pp2);
            }
        }
    }
}

// ---------------- K4: aggregation out[dst] += feat[src] * c ----------------
__global__ void __launch_bounds__(256) k_agg(const int* __restrict__ src,
                                             const int* __restrict__ dst,
                                             float* __restrict__ out) {
    int t = threadIdx.x;
    int wid = t >> 5, lane = t & 31;
    int e = blockIdx.x * 8 + wid;
    if (e >= Ee) return;
    int s = src[e], d = dst[e];
    float c = 0.f;
    if (lane < 8) {
        float sum = g_esum[d * 8 + lane];
        c = g_q[(size_t)e * 8 + lane] / sum;
    }
    const float4* fsrc = (const float4*)&g_feat[(size_t)s * 256];
    float* obase = &out[(size_t)d * 256];
#pragma unroll
    for (int i = 0; i < 2; i++) {
        int s4 = i * 32 + lane;                  // float4 slot, h = s4>>3
        float cc = __shfl_sync(0xffffffffu, c, s4 >> 3);
        float4 f = fsrc[s4];
        float* addr = obase + s4 * 4;
        asm volatile("red.global.add.v4.f32 [%0], {%1, %2, %3, %4};"
                     :: "l"(addr), "f"(f.x * cc), "f"(f.y * cc),
                        "f"(f.z * cc), "f"(f.w * cc)
                     : "memory");
    }
}

// ---------------- launch ----------------------------------------------------
extern "C" void kernel_launch(void* const* d_in, const int* in_sizes, int n_in,
                              void* d_out, int out_size) {
    const float* nfeat  = (const float*)d_in[0];
    const float* efeat  = (const float*)d_in[1];
    const float* rij    = (const float*)d_in[2];
    const int*   src    = (const int*)d_in[3];
    const int*   dst    = (const int*)d_in[4];
    const float* W_fc   = (const float*)d_in[5];
    const float* W_e1   = (const float*)d_in[6];
    const float* b_e1   = (const float*)d_in[7];
    const float* W_e2   = (const float*)d_in[8];
    const float* b_e2   = (const float*)d_in[9];
    const float* attn_l = (const float*)d_in[10];
    const float* attn_r = (const float*)d_in[11];
    const float* attn_e = (const float*)d_in[12];
    const float* bias   = (const float*)d_in[13];
    float* out = (float*)d_out;

    k_init<<<2048, 256>>>(out, bias);
    k_feat<<<dim3((Nn + 127) / 128, 4), 256>>>(nfeat, W_fc);
    k_elr<<<(Nn * 8 + 255) / 256, 256>>>(attn_l, attn_r);
    k_ef1<<<Ee / 256, 256>>>(efeat, W_e1, b_e1);
    k_edge<<<888, 256>>>(rij, src, dst, W_e2, b_e2, attn_e);
    k_agg<<<Ee / 8, 256>>>(src, dst, out);
}